// round 11
// baseline (speedup 1.0000x reference)
#include <cuda_runtime.h>
#include <cuda_fp16.h>
#include <cstdint>

// ---------------------------------------------------------------------------
// Problem dims
// ---------------------------------------------------------------------------
#define M_DIM 2048
#define N_DIM 8192
#define K_DIM 8192
#define NGROUPS ((N_DIM * K_DIM) / 8)   // 8388608

// Device-global scratch (no cudaMalloc allowed) — fp16 operands
__device__ __align__(256) __half g_w[(size_t)N_DIM * K_DIM];   // (N,K) row-major
__device__ __align__(256) __half g_x[(size_t)M_DIM * K_DIM];

// ---------------------------------------------------------------------------
// Prep: fp32 -> fp16, 8 elems/thread
// ---------------------------------------------------------------------------
__global__ void __launch_bounds__(256) xprep_kernel(const float* __restrict__ x) {
    size_t i = ((size_t)blockIdx.x * 256 + threadIdx.x) * 8;
    float4 v0 = *reinterpret_cast<const float4*>(x + i);
    float4 v1 = *reinterpret_cast<const float4*>(x + i + 4);
    union { __half2 h[4]; uint4 u; } o;
    o.h[0] = __floats2half2_rn(v0.x, v0.y);
    o.h[1] = __floats2half2_rn(v0.z, v0.w);
    o.h[2] = __floats2half2_rn(v1.x, v1.y);
    o.h[3] = __floats2half2_rn(v1.z, v1.w);
    *reinterpret_cast<uint4*>(g_x + i) = o.u;
}

// ---------------------------------------------------------------------------
// Zero-init the output (poisoned to 0xAA by the harness; split-K reduces into it)
// ---------------------------------------------------------------------------
__global__ void __launch_bounds__(256) yzero_kernel(float* __restrict__ y) {
    size_t i = ((size_t)blockIdx.x * 256 + threadIdx.x) * 4;
    *reinterpret_cast<float4*>(y + i) = make_float4(0.f, 0.f, 0.f, 0.f);
}

// ---------------------------------------------------------------------------
// Dequant: one 3-byte group -> 8 3-bit indices -> 8 fp16 weights (16B store)
// ---------------------------------------------------------------------------
__global__ void __launch_bounds__(256) dequant_kernel(const int* __restrict__ packed,
                                                      const float* __restrict__ codebook) {
    int g = blockIdx.x * 256 + threadIdx.x;
    int p0 = packed[3 * g + 0];
    int p1 = packed[3 * g + 1];
    int p2 = packed[3 * g + 2];
    unsigned bits = (unsigned)(p0 & 255) | ((unsigned)(p1 & 255) << 8) |
                    ((unsigned)(p2 & 255) << 16);
    const float* cb = codebook + ((size_t)(g >> 4)) * 8;
    union { __half h[8]; uint4 u; } o;
#pragma unroll
    for (int j = 0; j < 8; j++)
        o.h[j] = __float2half_rn(__ldg(cb + ((bits >> (3 * j)) & 7)));
    *reinterpret_cast<uint4*>(g_w + (size_t)g * 8) = o.u;
}

// ---------------------------------------------------------------------------
// GEMM: y[m,n] += sum_{k in half} x[m,k] * w[n,k]   (split-K = 2)
// BM=BN=128, BK=64 halves, 256 threads (8 warps 2x4, warp tile 64x32)
// 3-stage cp.async ring (wait_group 1), XOR-swizzled 128B rows, ldmatrix.x4.
// ---------------------------------------------------------------------------
#define BM 128
#define BN 128
#define BKH 64                          // k-halves per stage
#define KSPLIT 2
#define K_HALF (K_DIM / KSPLIT)         // 4096
#define K_TILES (K_HALF / BKH)          // 64
#define STAGES 3
#define STAGE_WORDS 8192                // (128+128) rows * 32 words
#define STAGE_BYTES 32768
#define B_OFF_BYTES 16384               // B region inside a stage
#define B_OFF_WORDS 4096

__device__ __forceinline__ void cp_async16(void* s, const void* g) {
    unsigned sa = (unsigned)__cvta_generic_to_shared(s);
    asm volatile("cp.async.cg.shared.global [%0], [%1], 16;\n" ::"r"(sa), "l"(g));
}

__device__ __forceinline__ void ldsm_x4(unsigned& r0, unsigned& r1, unsigned& r2,
                                        unsigned& r3, uint32_t addr) {
    asm volatile("ldmatrix.sync.aligned.m8n8.x4.shared.b16 {%0,%1,%2,%3}, [%4];"
                 : "=r"(r0), "=r"(r1), "=r"(r2), "=r"(r3) : "r"(addr));
}

__device__ __forceinline__ void mma_f16(float* c, const unsigned* a, const unsigned* b) {
    asm volatile(
        "mma.sync.aligned.m16n8k16.row.col.f32.f16.f16.f32 "
        "{%0,%1,%2,%3}, {%4,%5,%6,%7}, {%8,%9}, {%0,%1,%2,%3};\n"
        : "+f"(c[0]), "+f"(c[1]), "+f"(c[2]), "+f"(c[3])
        : "r"(a[0]), "r"(a[1]), "r"(a[2]), "r"(a[3]), "r"(b[0]), "r"(b[1]));
}

__device__ __forceinline__ void red_add_f32(float* addr, float v) {
    asm volatile("red.global.add.f32 [%0], %1;" :: "l"(addr), "f"(v) : "memory");
}

__global__ void __launch_bounds__(256, 2) gemm_kernel(float* __restrict__ y) {
    extern __shared__ unsigned smem[];          // [STAGES][8192] b32 words
    const uint32_t smem_sa = (uint32_t)__cvta_generic_to_shared(smem);

    const int tid = threadIdx.x;
    const int wid = tid >> 5;
    const int lane = tid & 31;
    const int wm = wid >> 2;        // 0..1
    const int wn = wid & 3;         // 0..3
    const int gr = lane >> 2;       // 0..7
    const int tg = lane & 3;        // 0..3
    const int l7 = lane & 7;

    const int m0 = blockIdx.x * BM;   // m-fastest rasterization: B panels L2-resident
    const int n0 = blockIdx.y * BN;
    const int k0 = blockIdx.z * K_HALF;
    const __half* Ag = g_x + (size_t)m0 * K_DIM + k0;
    const __half* Bg = g_w + (size_t)n0 * K_DIM + k0;

    // per-lane fixed pieces of the ldmatrix addressing
    const int hiA = lane >> 4;                       // A k-half selector
    const int hiB = (lane >> 3) & 1;                 // B k-half selector
    const uint32_t a_row_b = (uint32_t)(wm * 64 + (lane & 15)) * 128;
    const uint32_t b_row_b = (uint32_t)(wn * 32 + (lane & 7) + (lane >> 4) * 8) * 128;

    float acc[4][4][4];
#pragma unroll
    for (int i = 0; i < 4; i++)
#pragma unroll
        for (int j = 0; j < 4; j++)
#pragma unroll
            for (int r = 0; r < 4; r++) acc[i][j][r] = 0.0f;

    // tile loader: 128 rows x 128B per matrix; chunk stored at (ch ^ (row&7))
    auto load_tile = [&](int kt, int st) {
        const __half* a = Ag + kt * BKH;
        const __half* b = Bg + kt * BKH;
        unsigned* sb = smem + st * STAGE_WORDS;
#pragma unroll
        for (int i = 0; i < 4; i++) {
            int f = tid + i * 256;            // 0..1023
            int row = f >> 3;
            int ch = f & 7;
            int sw = (ch ^ (row & 7)) * 4;    // swizzled word offset in row
            cp_async16(sb + row * 32 + sw, a + (size_t)row * K_DIM + ch * 8);
            cp_async16(sb + B_OFF_WORDS + row * 32 + sw, b + (size_t)row * K_DIM + ch * 8);
        }
    };

    auto compute = [&](int st) {
        const uint32_t sa = smem_sa + (uint32_t)st * STAGE_BYTES;
#pragma unroll
        for (int ks = 0; ks < 4; ks++) {       // 4 x k16 steps per BK=64
            const uint32_t swA = (uint32_t)(((2 * ks + hiA) ^ l7) << 4);
            const uint32_t swB = (uint32_t)(((2 * ks + hiB) ^ l7) << 4);
            unsigned a[4][4], b[4][2];
#pragma unroll
            for (int jp = 0; jp < 2; jp++)
                ldsm_x4(b[2 * jp][0], b[2 * jp][1], b[2 * jp + 1][0], b[2 * jp + 1][1],
                        sa + B_OFF_BYTES + b_row_b + (uint32_t)(jp * 16 * 128) + swB);
#pragma unroll
            for (int i = 0; i < 4; i++)
                ldsm_x4(a[i][0], a[i][1], a[i][2], a[i][3],
                        sa + a_row_b + (uint32_t)(i * 16 * 128) + swA);
#pragma unroll
            for (int i = 0; i < 4; i++)
#pragma unroll
                for (int j = 0; j < 4; j++) mma_f16(acc[i][j], a[i], b[j]);
        }
    };

    // ---- 3-stage pipelined mainloop (CUTLASS multistage ordering) ----
    load_tile(0, 0);
    asm volatile("cp.async.commit_group;\n");
    load_tile(1, 1);
    asm volatile("cp.async.commit_group;\n");

    int ld_st = 2, cp_st = 0;
#pragma unroll 1
    for (int kt = 0; kt < K_TILES; kt++) {
        asm volatile("cp.async.wait_group 1;\n");
        __syncthreads();                       // stage kt visible; compute(kt-1) done by all
        if (kt + 2 < K_TILES) load_tile(kt + 2, ld_st);
        asm volatile("cp.async.commit_group;\n");
        compute(cp_st);
        ld_st = (ld_st == STAGES - 1) ? 0 : ld_st + 1;
        cp_st = (cp_st == STAGES - 1) ? 0 : cp_st + 1;
    }

    // epilogue: reduce into y (two commutative fp32 adds per element -> deterministic)
#pragma unroll
    for (int i = 0; i < 4; i++) {
#pragma unroll
        for (int j = 0; j < 4; j++) {
            int row = m0 + wm * 64 + i * 16 + gr;
            int col = n0 + wn * 32 + j * 8 + tg * 2;
            float* p0 = y + (size_t)row * N_DIM + col;
            float* p1 = y + (size_t)(row + 8) * N_DIM + col;
            red_add_f32(p0 + 0, acc[i][j][0]);
            red_add_f32(p0 + 1, acc[i][j][1]);
            red_add_f32(p1 + 0, acc[i][j][2]);
            red_add_f32(p1 + 1, acc[i][j][3]);
        }
    }
}

// ---------------------------------------------------------------------------
// Launch
// ---------------------------------------------------------------------------
extern "C" void kernel_launch(void* const* d_in, const int* in_sizes, int n_in,
                              void* d_out, int out_size) {
    const float* x = nullptr;
    const int* packed = nullptr;
    const float* codebook = nullptr;
    for (int i = 0; i < n_in; i++) {
        if (in_sizes[i] == M_DIM * K_DIM) x = (const float*)d_in[i];
        else if (in_sizes[i] == NGROUPS * 3) packed = (const int*)d_in[i];
        else codebook = (const float*)d_in[i];
    }
    float* y = (float*)d_out;

    yzero_kernel<<<((size_t)M_DIM * N_DIM) / (256 * 4), 256>>>(y);
    xprep_kernel<<<(M_DIM * (size_t)K_DIM) / (256 * 8), 256>>>(x);
    dequant_kernel<<<NGROUPS / 256, 256>>>(packed, codebook);

    const int smem_bytes = STAGES * STAGE_BYTES;   // 98304
    cudaFuncSetAttribute(gemm_kernel, cudaFuncAttributeMaxDynamicSharedMemorySize, smem_bytes);
    dim3 grid(M_DIM / BM, N_DIM / BN, KSPLIT);   // (16, 64, 2) = 2048 CTAs
    gemm_kernel<<<grid, 256, smem_bytes>>>(y);
}

// round 13
// speedup vs baseline: 1.1299x; 1.1299x over previous
#include <cuda_runtime.h>
#include <cuda_fp16.h>
#include <cstdint>

// ---------------------------------------------------------------------------
// Problem dims
// ---------------------------------------------------------------------------
#define M_DIM 2048
#define N_DIM 8192
#define K_DIM 8192
#define NGROUPS ((N_DIM * K_DIM) / 8)   // 8388608

// Device-global scratch (no cudaMalloc allowed) — fp16 operands
__device__ __align__(256) __half g_w[(size_t)N_DIM * K_DIM];   // (N,K) row-major
__device__ __align__(256) __half g_x[(size_t)M_DIM * K_DIM];

// ---------------------------------------------------------------------------
// Prep: fp32 -> fp16, 8 elems/thread
// ---------------------------------------------------------------------------
__global__ void __launch_bounds__(256) xprep_kernel(const float* __restrict__ x) {
    size_t i = ((size_t)blockIdx.x * 256 + threadIdx.x) * 8;
    float4 v0 = *reinterpret_cast<const float4*>(x + i);
    float4 v1 = *reinterpret_cast<const float4*>(x + i + 4);
    union { __half2 h[4]; uint4 u; } o;
    o.h[0] = __floats2half2_rn(v0.x, v0.y);
    o.h[1] = __floats2half2_rn(v0.z, v0.w);
    o.h[2] = __floats2half2_rn(v1.x, v1.y);
    o.h[3] = __floats2half2_rn(v1.z, v1.w);
    *reinterpret_cast<uint4*>(g_x + i) = o.u;
}

// ---------------------------------------------------------------------------
// Dequant: one 3-byte group -> 8 3-bit indices -> 8 fp16 weights (16B store)
// ---------------------------------------------------------------------------
__global__ void __launch_bounds__(256) dequant_kernel(const int* __restrict__ packed,
                                                      const float* __restrict__ codebook) {
    int g = blockIdx.x * 256 + threadIdx.x;
    int p0 = packed[3 * g + 0];
    int p1 = packed[3 * g + 1];
    int p2 = packed[3 * g + 2];
    unsigned bits = (unsigned)(p0 & 255) | ((unsigned)(p1 & 255) << 8) |
                    ((unsigned)(p2 & 255) << 16);
    const float* cb = codebook + ((size_t)(g >> 4)) * 8;
    union { __half h[8]; uint4 u; } o;
#pragma unroll
    for (int j = 0; j < 8; j++)
        o.h[j] = __float2half_rn(__ldg(cb + ((bits >> (3 * j)) & 7)));
    *reinterpret_cast<uint4*>(g_w + (size_t)g * 8) = o.u;
}

// ---------------------------------------------------------------------------
// GEMM: y[m,n] = sum_k x[m,k] * w[n,k]   fp16 inputs, fp32 accumulate
// BM=BN=128, BK=64 halves, 128 threads (4 warps 2x2, warp tile 64x64)
// 3-stage cp.async ring (wait_group 1), XOR-swizzled 128B rows, ldmatrix.x4.
// ---------------------------------------------------------------------------
#define BM 128
#define BN 128
#define BKH 64                          // k-halves per stage
#define K_TILES (K_DIM / BKH)           // 128
#define STAGES 3
#define STAGE_WORDS 8192                // (128+128) rows * 32 words
#define STAGE_BYTES 32768
#define B_OFF_BYTES 16384               // B region inside a stage
#define B_OFF_WORDS 4096

__device__ __forceinline__ void cp_async16(void* s, const void* g) {
    unsigned sa = (unsigned)__cvta_generic_to_shared(s);
    asm volatile("cp.async.cg.shared.global [%0], [%1], 16;\n" ::"r"(sa), "l"(g));
}

__device__ __forceinline__ void ldsm_x4(unsigned& r0, unsigned& r1, unsigned& r2,
                                        unsigned& r3, uint32_t addr) {
    asm volatile("ldmatrix.sync.aligned.m8n8.x4.shared.b16 {%0,%1,%2,%3}, [%4];"
                 : "=r"(r0), "=r"(r1), "=r"(r2), "=r"(r3) : "r"(addr));
}

__device__ __forceinline__ void mma_f16(float* c, const unsigned* a, const unsigned* b) {
    asm volatile(
        "mma.sync.aligned.m16n8k16.row.col.f32.f16.f16.f32 "
        "{%0,%1,%2,%3}, {%4,%5,%6,%7}, {%8,%9}, {%0,%1,%2,%3};\n"
        : "+f"(c[0]), "+f"(c[1]), "+f"(c[2]), "+f"(c[3])
        : "r"(a[0]), "r"(a[1]), "r"(a[2]), "r"(a[3]), "r"(b[0]), "r"(b[1]));
}

__global__ void __launch_bounds__(128, 2) gemm_kernel(float* __restrict__ y) {
    extern __shared__ unsigned smem[];          // [STAGES][8192] b32 words
    const uint32_t smem_sa = (uint32_t)__cvta_generic_to_shared(smem);

    const int tid = threadIdx.x;
    const int wid = tid >> 5;
    const int lane = tid & 31;
    const int wm = wid >> 1;        // 0..1  (64-row warp tile)
    const int wn = wid & 1;         // 0..1  (64-col warp tile)
    const int gr = lane >> 2;       // 0..7
    const int tg = lane & 3;        // 0..3
    const int l7 = lane & 7;

    const int m0 = blockIdx.x * BM;   // m-fastest rasterization: B panels L2-resident
    const int n0 = blockIdx.y * BN;
    const __half* Ag = g_x + (size_t)m0 * K_DIM;
    const __half* Bg = g_w + (size_t)n0 * K_DIM;

    // per-lane fixed pieces of the ldmatrix addressing
    const int hiA = lane >> 4;                       // A k-half selector
    const int hiB = (lane >> 3) & 1;                 // B k-half selector
    const uint32_t a_row_b = (uint32_t)(wm * 64 + (lane & 15)) * 128;
    const uint32_t b_row_b = (uint32_t)(wn * 64 + (lane & 7) + (lane >> 4) * 8) * 128;

    float acc[4][8][4];
#pragma unroll
    for (int i = 0; i < 4; i++)
#pragma unroll
        for (int j = 0; j < 8; j++)
#pragma unroll
            for (int r = 0; r < 4; r++) acc[i][j][r] = 0.0f;

    // tile loader: 128 rows x 128B per matrix; chunk stored at (ch ^ (row&7))
    auto load_tile = [&](int kt, int st) {
        const __half* a = Ag + kt * BKH;
        const __half* b = Bg + kt * BKH;
        unsigned* sb = smem + st * STAGE_WORDS;
#pragma unroll
        for (int i = 0; i < 8; i++) {
            int f = tid + i * 128;            // 0..1023
            int row = f >> 3;
            int ch = f & 7;
            int sw = (ch ^ (row & 7)) * 4;    // swizzled word offset in row
            cp_async16(sb + row * 32 + sw, a + (size_t)row * K_DIM + ch * 8);
            cp_async16(sb + B_OFF_WORDS + row * 32 + sw, b + (size_t)row * K_DIM + ch * 8);
        }
    };

    auto compute = [&](int st) {
        const uint32_t sa = smem_sa + (uint32_t)st * STAGE_BYTES;
#pragma unroll
        for (int ks = 0; ks < 4; ks++) {       // 4 x k16 steps per BK=64
            const uint32_t swA = (uint32_t)(((2 * ks + hiA) ^ l7) << 4);
            const uint32_t swB = (uint32_t)(((2 * ks + hiB) ^ l7) << 4);
            unsigned a[4][4], b[8][2];
#pragma unroll
            for (int jp = 0; jp < 4; jp++)
                ldsm_x4(b[2 * jp][0], b[2 * jp][1], b[2 * jp + 1][0], b[2 * jp + 1][1],
                        sa + B_OFF_BYTES + b_row_b + (uint32_t)(jp * 16 * 128) + swB);
#pragma unroll
            for (int i = 0; i < 4; i++)
                ldsm_x4(a[i][0], a[i][1], a[i][2], a[i][3],
                        sa + a_row_b + (uint32_t)(i * 16 * 128) + swA);
#pragma unroll
            for (int i = 0; i < 4; i++)
#pragma unroll
                for (int j = 0; j < 8; j++) mma_f16(acc[i][j], a[i], b[j]);
        }
    };

    // ---- 3-stage pipelined mainloop (CUTLASS multistage ordering) ----
    load_tile(0, 0);
    asm volatile("cp.async.commit_group;\n");
    load_tile(1, 1);
    asm volatile("cp.async.commit_group;\n");

    int ld_st = 2, cp_st = 0;
#pragma unroll 1
    for (int kt = 0; kt < K_TILES; kt++) {
        asm volatile("cp.async.wait_group 1;\n");
        __syncthreads();                       // stage kt visible; compute(kt-1) done by all
        if (kt + 2 < K_TILES) load_tile(kt + 2, ld_st);
        asm volatile("cp.async.commit_group;\n");
        compute(cp_st);
        ld_st = (ld_st == STAGES - 1) ? 0 : ld_st + 1;
        cp_st = (cp_st == STAGES - 1) ? 0 : cp_st + 1;
    }

    // epilogue: fp32 accumulators straight to gmem
#pragma unroll
    for (int i = 0; i < 4; i++) {
#pragma unroll
        for (int j = 0; j < 8; j++) {
            int row = m0 + wm * 64 + i * 16 + gr;
            int col = n0 + wn * 64 + j * 8 + tg * 2;
            *reinterpret_cast<float2*>(y + (size_t)row * N_DIM + col) =
                make_float2(acc[i][j][0], acc[i][j][1]);
            *reinterpret_cast<float2*>(y + (size_t)(row + 8) * N_DIM + col) =
                make_float2(acc[i][j][2], acc[i][j][3]);
        }
    }
}

// ---------------------------------------------------------------------------
// Launch
// ---------------------------------------------------------------------------
extern "C" void kernel_launch(void* const* d_in, const int* in_sizes, int n_in,
                              void* d_out, int out_size) {
    const float* x = nullptr;
    const int* packed = nullptr;
    const float* codebook = nullptr;
    for (int i = 0; i < n_in; i++) {
        if (in_sizes[i] == M_DIM * K_DIM) x = (const float*)d_in[i];
        else if (in_sizes[i] == NGROUPS * 3) packed = (const int*)d_in[i];
        else codebook = (const float*)d_in[i];
    }
    float* y = (float*)d_out;

    xprep_kernel<<<(M_DIM * (size_t)K_DIM) / (256 * 8), 256>>>(x);
    dequant_kernel<<<NGROUPS / 256, 256>>>(packed, codebook);

    const int smem_bytes = STAGES * STAGE_BYTES;   // 98304
    cudaFuncSetAttribute(gemm_kernel, cudaFuncAttributeMaxDynamicSharedMemorySize, smem_bytes);
    dim3 grid(M_DIM / BM, N_DIM / BN);   // (16, 64), m-fastest
    gemm_kernel<<<grid, 128, smem_bytes>>>(y);
}